// round 14
// baseline (speedup 1.0000x reference)
#include <cuda_runtime.h>
#include <cuda_bf16.h>
#include <cuda_fp16.h>
#include <math.h>
#include <stdint.h>

#define BB 8
#define NN 512
#define CC 1024
#define HH 16
#define HD 64
#define LL 6
#define FF 4096
#define OUTD 2
#define MM (BB*NN)
#define BHN (BB*HH)
#define LOG2E 1.44269504088896f

// gemm_1p tiling: 128x256x32, 512 threads (4m x 4n warps, warp tile 32x64)
#define ROWB 80
#define OFF_B 10240
#define STAGE_SB 30720
#define DYN_SB (2*STAGE_SB)   // 61440

// weight offsets (elements)
#define OFF_WI   0ULL
#define OFF_WQKV 1048576ULL
#define OFF_WO   19922944ULL
#define OFF_W1   26214400ULL
#define OFF_W2   51380224ULL
#define WELEMS   76546048ULL

#define FLD 68
#define FLASH_SB (4*64*FLD*4)

// ---- scratch ----
__device__ float g_x [MM*CC];
__device__ float g_q [BHN*NN*HD];
__device__ float g_k [BHN*NN*HD];
__device__ float g_v [BHN*NN*HD];
__device__ __half g_ah[MM*CC];
__device__ __half g_fh[MM*FF];
__device__ __half g_wh[WELEMS];

__device__ __forceinline__ uint32_t smem_u32(const void* p) {
    uint32_t a;
    asm("{ .reg .u64 t; cvta.to.shared.u64 t, %1; cvt.u32.u64 %0, t; }" : "=r"(a) : "l"(p));
    return a;
}
__device__ __forceinline__ void ldsm4(uint32_t& r0, uint32_t& r1, uint32_t& r2, uint32_t& r3, uint32_t a) {
    asm volatile("ldmatrix.sync.aligned.m8n8.x4.shared.b16 {%0,%1,%2,%3},[%4];"
                 : "=r"(r0), "=r"(r1), "=r"(r2), "=r"(r3) : "r"(a));
}
__device__ __forceinline__ void mma_f16(float* c, const uint32_t* a, const uint32_t* b) {
    asm volatile(
        "mma.sync.aligned.m16n8k16.row.col.f32.f16.f16.f32 "
        "{%0,%1,%2,%3},{%4,%5,%6,%7},{%8,%9},{%0,%1,%2,%3};"
        : "+f"(c[0]), "+f"(c[1]), "+f"(c[2]), "+f"(c[3])
        : "r"(a[0]), "r"(a[1]), "r"(a[2]), "r"(a[3]), "r"(b[0]), "r"(b[1]));
}
__device__ __forceinline__ float gelu1(float v) {
    return 0.5f * v * (1.0f + erff(v * 0.70710678118654752f));
}
__device__ __forceinline__ unsigned long long pack2(float x, float y) {
    unsigned long long r;
    asm("mov.b64 %0, {%1, %2};" : "=l"(r) : "f"(x), "f"(y));
    return r;
}
__device__ __forceinline__ void fma2(unsigned long long& d, unsigned long long a, unsigned long long b) {
    asm("fma.rn.f32x2 %0, %1, %2, %0;" : "+l"(d) : "l"(a), "l"(b));
}
__device__ __forceinline__ void mul2(unsigned long long& d, unsigned long long a) {
    asm("mul.rn.f32x2 %0, %0, %1;" : "+l"(d) : "l"(a));
}
union U64F2 { unsigned long long u; float2 f; };

// fp16 GEMM: C = Ah*Bh + bias
// MODE: 1=OUT_POS 2=QKV scatter 3=RESID 4=GELU_H
template<int MODE>
__global__ void __launch_bounds__(512, 1)
gemm_1p(const __half* __restrict__ Ah, const __half* __restrict__ Bh,
        const float* __restrict__ bias, float* __restrict__ C,
        __half* __restrict__ oh,
        const float* __restrict__ pos,
        float* __restrict__ qp, float* __restrict__ kp, float* __restrict__ vp,
        int Nn, int K)
{
    extern __shared__ unsigned char sm[];
    const uint32_t sbase = smem_u32(sm);
    const int tid = threadIdx.x, lane = tid & 31, wid = tid >> 5;
    const int wm = wid & 3, wn = wid >> 2;
    const int bm = blockIdx.y * 128, bn = blockIdx.x * 256;
    const int nc = K >> 5;

    auto load_stage = [&](int buf, int chunk) {
        const int k0 = chunk * 32;
        const uint32_t sb = sbase + buf * STAGE_SB;
        {
            int r = tid >> 2, seg = tid & 3;
            const __half* gA = Ah + (size_t)(bm + r) * K + k0 + seg * 8;
            uint32_t s = sb + r * ROWB + seg * 16;
            asm volatile("cp.async.cg.shared.global [%0], [%1], 16;" :: "r"(s), "l"(gA));
        }
#pragma unroll
        for (int j = 0; j < 2; j++) {
            int idx = tid + 512 * j;
            int r = idx >> 2, seg = idx & 3;
            const __half* gB = Bh + (size_t)(bn + r) * K + k0 + seg * 8;
            uint32_t s = sb + OFF_B + r * ROWB + seg * 16;
            asm volatile("cp.async.cg.shared.global [%0], [%1], 16;" :: "r"(s), "l"(gB));
        }
        asm volatile("cp.async.commit_group;");
    };

    float acc[2][8][4] = {};

    load_stage(0, 0);
    load_stage(1, 1);
    asm volatile("cp.async.wait_group 1;");
    __syncthreads();

    const uint32_t brow = ((lane >> 4) << 3) + (lane & 7);
    for (int c = 0; c < nc; c++) {
        const uint32_t sb = sbase + (c & 1) * STAGE_SB;
#pragma unroll
        for (int k16 = 0; k16 < 2; k16++) {
            uint32_t bh[8][2];
            const uint32_t bcol = k16 * 32 + ((lane >> 3) & 1) * 16;
#pragma unroll
            for (int ntp = 0; ntp < 4; ntp++) {
                uint32_t bd = sb + OFF_B + (wn * 64 + ntp * 16 + brow) * ROWB + bcol;
                ldsm4(bh[2*ntp][0], bh[2*ntp][1], bh[2*ntp+1][0], bh[2*ntp+1][1], bd);
            }
            const uint32_t acol = k16 * 32 + (lane >> 4) * 16;
#pragma unroll
            for (int mt = 0; mt < 2; mt++) {
                uint32_t ah4[4];
                uint32_t ad = sb + (wm * 32 + mt * 16 + (lane & 15)) * ROWB + acol;
                ldsm4(ah4[0], ah4[1], ah4[2], ah4[3], ad);
#pragma unroll
                for (int nt = 0; nt < 8; nt++) mma_f16(acc[mt][nt], ah4, bh[nt]);
            }
        }
        __syncthreads();
        if (c + 2 < nc) load_stage(c & 1, c + 2);
        asm volatile("cp.async.wait_group 1;");
        __syncthreads();
    }

    const int tr = lane >> 2, tc = (lane & 3) * 2;
#pragma unroll
    for (int mt = 0; mt < 2; mt++) {
        const int rb = bm + wm * 32 + mt * 16 + tr;
#pragma unroll
        for (int nt = 0; nt < 8; nt++) {
            const int c0 = bn + wn * 64 + nt * 8 + tc;
            const float b0 = bias[c0], b1 = bias[c0 + 1];
#pragma unroll
            for (int hrow = 0; hrow < 2; hrow++) {
                const int r = rb + hrow * 8;
                float v0 = acc[mt][nt][2 * hrow]     + b0;
                float v1 = acc[mt][nt][2 * hrow + 1] + b1;
                if (MODE == 1) {
                    const float2 pp = *reinterpret_cast<const float2*>(&pos[(size_t)(r & 511) * CC + c0]);
                    float2 o = { v0 + pp.x, v1 + pp.y };
                    *reinterpret_cast<float2*>(&C[(size_t)r * CC + c0]) = o;
                } else if (MODE == 2) {
                    const int which = c0 >> 10, ci = c0 & 1023;
                    const int head = ci >> 6, hd = ci & 63;
                    const int bb2 = r >> 9, n = r & 511;
                    const size_t off = ((size_t)(bb2 * HH + head) * NN + n) * HD + hd;
                    if (which == 0) {
                        float2 o = { v0 * 0.125f, v1 * 0.125f };
                        *reinterpret_cast<float2*>(&qp[off]) = o;
                    } else if (which == 1) {
                        float2 o = { v0, v1 };
                        *reinterpret_cast<float2*>(&kp[off]) = o;
                    } else {
                        float2 o = { v0, v1 };
                        *reinterpret_cast<float2*>(&vp[off]) = o;
                    }
                } else if (MODE == 3) {
                    float2* p = reinterpret_cast<float2*>(&C[(size_t)r * Nn + c0]);
                    float2 old = *p;
                    old.x += v0; old.y += v1;
                    *p = old;
                } else {
                    __half2 hh;
                    hh.x = __float2half_rn(gelu1(v0));
                    hh.y = __float2half_rn(gelu1(v1));
                    *reinterpret_cast<__half2*>(&oh[(size_t)r * Nn + c0]) = hh;
                }
            }
        }
    }
}

// ---- fused flash attention (f32x2), fp16 output ----
__global__ void __launch_bounds__(256, 2)
flash_k(const float* __restrict__ q, const float* __restrict__ k, const float* __restrict__ v,
        const int* __restrict__ mask, __half* __restrict__ oh)
{
    extern __shared__ float fs[];
    float* QsT = fs;
    float* KsT = fs + 64 * FLD;
    float* Vs  = fs + 2 * 64 * FLD;
    float* PsT = fs + 3 * 64 * FLD;
    __shared__ int msk[64];

    const int tid = threadIdx.x, tx = tid & 15, ty = tid >> 4;
    const int bh = blockIdx.y, b = bh >> 4, head = bh & 15;
    const int q0 = blockIdx.x * 64;
    const float* qbase = q + ((size_t)bh * NN + q0) * HD;
    const float* kbase = k + (size_t)bh * NN * HD;
    const float* vbase = v + (size_t)bh * NN * HD;

#pragma unroll
    for (int i = 0; i < 4; i++) {
        int idx = tid + 256 * i;
        int row = idx >> 4, c4 = (idx & 15) * 4;
        float4 qq = *reinterpret_cast<const float4*>(qbase + row * HD + c4);
        QsT[(c4 + 0) * FLD + row] = qq.x;
        QsT[(c4 + 1) * FLD + row] = qq.y;
        QsT[(c4 + 2) * FLD + row] = qq.z;
        QsT[(c4 + 3) * FLD + row] = qq.w;
    }

    unsigned long long O2[4][2] = {};
    float m[4] = {-3.0e38f, -3.0e38f, -3.0e38f, -3.0e38f};
    float l[4] = {};

    for (int kc = 0; kc < 8; kc++) {
        __syncthreads();
#pragma unroll
        for (int i = 0; i < 4; i++) {
            int idx = tid + 256 * i;
            int row = idx >> 4, c4 = (idx & 15) * 4;
            float4 kk4 = *reinterpret_cast<const float4*>(kbase + (size_t)(kc * 64 + row) * HD + c4);
            KsT[(c4 + 0) * FLD + row] = kk4.x;
            KsT[(c4 + 1) * FLD + row] = kk4.y;
            KsT[(c4 + 2) * FLD + row] = kk4.z;
            KsT[(c4 + 3) * FLD + row] = kk4.w;
            float4 vv4 = *reinterpret_cast<const float4*>(vbase + (size_t)(kc * 64 + row) * HD + c4);
            *reinterpret_cast<float4*>(Vs + row * FLD + c4) = vv4;
        }
        if (tid < 64) msk[tid] = mask[b * NN + kc * 64 + tid];
        __syncthreads();

        unsigned long long s2[4][2] = {};
        for (int kk = 0; kk < 64; kk++) {
            float4 q4 = *reinterpret_cast<float4*>(QsT + kk * FLD + 4 * ty);
            float4 k4 = *reinterpret_cast<float4*>(KsT + kk * FLD + 4 * tx);
            unsigned long long kp0 = pack2(k4.x, k4.y), kp1 = pack2(k4.z, k4.w);
            float qa[4] = {q4.x, q4.y, q4.z, q4.w};
#pragma unroll
            for (int i = 0; i < 4; i++) {
                unsigned long long qq = pack2(qa[i], qa[i]);
                fma2(s2[i][0], qq, kp0);
                fma2(s2[i][1], qq, kp1);
            }
        }
        float s[4][4];
#pragma unroll
        for (int i = 0; i < 4; i++) {
            U64F2 u0, u1; u0.u = s2[i][0]; u1.u = s2[i][1];
            s[i][0] = u0.f.x; s[i][1] = u0.f.y; s[i][2] = u1.f.x; s[i][3] = u1.f.y;
        }
#pragma unroll
        for (int j = 0; j < 4; j++)
            if (msk[4 * tx + j] == 0) { s[0][j] = -1e9f; s[1][j] = -1e9f; s[2][j] = -1e9f; s[3][j] = -1e9f; }

#pragma unroll
        for (int i = 0; i < 4; i++) {
            float cm = fmaxf(fmaxf(s[i][0], s[i][1]), fmaxf(s[i][2], s[i][3]));
#pragma unroll
            for (int o = 8; o > 0; o >>= 1) cm = fmaxf(cm, __shfl_xor_sync(0xffffffffu, cm, o));
            float mn = fmaxf(m[i], cm);
            float corr = exp2f((m[i] - mn) * LOG2E);
            m[i] = mn;
            float rs = 0.0f;
#pragma unroll
            for (int j = 0; j < 4; j++) { s[i][j] = exp2f((s[i][j] - mn) * LOG2E); rs += s[i][j]; }
#pragma unroll
            for (int o = 8; o > 0; o >>= 1) rs += __shfl_xor_sync(0xffffffffu, rs, o);
            l[i] = l[i] * corr + rs;
            unsigned long long cp = pack2(corr, corr);
            mul2(O2[i][0], cp);
            mul2(O2[i][1], cp);
        }
#pragma unroll
        for (int j = 0; j < 4; j++) {
            float4 pv = { s[0][j], s[1][j], s[2][j], s[3][j] };
            *reinterpret_cast<float4*>(PsT + (4 * tx + j) * FLD + 4 * ty) = pv;
        }
        __syncthreads();

        for (int kk = 0; kk < 64; kk++) {
            float4 p4 = *reinterpret_cast<float4*>(PsT + kk * FLD + 4 * ty);
            float4 v4 = *reinterpret_cast<float4*>(Vs + kk * FLD + 4 * tx);
            unsigned long long vp0 = pack2(v4.x, v4.y), vp1 = pack2(v4.z, v4.w);
            float pa[4] = {p4.x, p4.y, p4.z, p4.w};
#pragma unroll
            for (int i = 0; i < 4; i++) {
                unsigned long long pp = pack2(pa[i], pa[i]);
                fma2(O2[i][0], pp, vp0);
                fma2(O2[i][1], pp, vp1);
            }
        }
    }

#pragma unroll
    for (int i = 0; i < 4; i++) {
        float inv = 1.0f / l[i];
        U64F2 u0, u1; u0.u = O2[i][0]; u1.u = O2[i][1];
        const size_t off = ((size_t)(b * NN + q0 + 4 * ty + i)) * CC + head * HD + 4 * tx;
        __half2 hA, hB;
        hA.x = __float2half_rn(u0.f.x * inv); hA.y = __float2half_rn(u0.f.y * inv);
        hB.x = __float2half_rn(u1.f.x * inv); hB.y = __float2half_rn(u1.f.y * inv);
        *reinterpret_cast<__half2*>(&oh[off])     = hA;
        *reinterpret_cast<__half2*>(&oh[off + 2]) = hB;
    }
}

// ---- reductions / elementwise ----
template<bool MAXRED>
__device__ __forceinline__ float blockReduce(float val) {
    __shared__ float sh[32];
    __syncthreads();
#pragma unroll
    for (int o = 16; o > 0; o >>= 1) {
        float t = __shfl_xor_sync(0xffffffffu, val, o);
        val = MAXRED ? fmaxf(val, t) : val + t;
    }
    int w = threadIdx.x >> 5, ln = threadIdx.x & 31;
    if (ln == 0) sh[w] = val;
    __syncthreads();
    int nw = blockDim.x >> 5;
    if (threadIdx.x < 32) {
        val = (ln < nw) ? sh[ln] : (MAXRED ? -3.4e38f : 0.0f);
#pragma unroll
        for (int o = 16; o > 0; o >>= 1) {
            float t = __shfl_xor_sync(0xffffffffu, val, o);
            val = MAXRED ? fmaxf(val, t) : val + t;
        }
        if (ln == 0) sh[0] = val;
    }
    __syncthreads();
    return sh[0];
}

__global__ void layernorm_h_k(const float* __restrict__ x, const float* __restrict__ g,
                              const float* __restrict__ b, __half* __restrict__ oh)
{
    int row = blockIdx.x, tid = threadIdx.x;
    const float* xr = x + (size_t)row * CC;
    float4 vv = *reinterpret_cast<const float4*>(xr + tid * 4);
    float s = blockReduce<false>(vv.x + vv.y + vv.z + vv.w);
    float mu = s * (1.0f / CC);
    float d0 = vv.x - mu, d1 = vv.y - mu, d2 = vv.z - mu, d3 = vv.w - mu;
    float s2 = blockReduce<false>(d0*d0 + d1*d1 + d2*d2 + d3*d3);
    float inv = rsqrtf(s2 * (1.0f / CC) + 1e-6f);
    float4 gg = *reinterpret_cast<const float4*>(g + tid * 4);
    float4 bb = *reinterpret_cast<const float4*>(b + tid * 4);
    __half2 hA, hB;
    hA.x = __float2half_rn(d0 * inv * gg.x + bb.x);
    hA.y = __float2half_rn(d1 * inv * gg.y + bb.y);
    hB.x = __float2half_rn(d2 * inv * gg.z + bb.z);
    hB.y = __float2half_rn(d3 * inv * gg.w + bb.w);
    size_t off = (size_t)row * CC + tid * 4;
    *reinterpret_cast<__half2*>(&oh[off])     = hA;
    *reinterpret_cast<__half2*>(&oh[off + 2]) = hB;
}

__global__ void tohalf_k(const float4* __restrict__ s, __half2* __restrict__ h, int n4) {
    int i = blockIdx.x * blockDim.x + threadIdx.x;
    if (i < n4) {
        float4 v = s[i];
        __half2 hA, hB;
        hA.x = __float2half_rn(v.x); hA.y = __float2half_rn(v.y);
        hB.x = __float2half_rn(v.z); hB.y = __float2half_rn(v.w);
        h[2 * i] = hA; h[2 * i + 1] = hB;
    }
}

__global__ void final_k(const float* __restrict__ x, const float* __restrict__ Wout,
                        const float* __restrict__ bout, float* __restrict__ out) {
    int mrow = blockIdx.x, j = threadIdx.x >> 5, lane = threadIdx.x & 31;
    const float* xr = x + (size_t)mrow * CC;
    const float* w  = Wout + (size_t)j * CC;
    float s = 0.0f;
#pragma unroll
    for (int t = 0; t < CC / 32; t++) s += xr[lane + 32 * t] * w[lane + 32 * t];
#pragma unroll
    for (int o = 16; o > 0; o >>= 1) s += __shfl_xor_sync(0xffffffffu, s, o);
    if (lane == 0) out[mrow * OUTD + j] = 1.0f / (1.0f + expf(-(s + bout[j])));
}

// ---- host ----
static inline dim3 eg4(int total) { return dim3((total / 4 + 255) / 256); }

extern "C" void kernel_launch(void* const* d_in, const int* in_sizes, int n_in,
                              void* d_out, int out_size)
{
    (void)in_sizes; (void)n_in; (void)out_size;
    const float* inputs = (const float*)d_in[0];
    const int*   mask   = (const int*)  d_in[1];
    const float* pos    = (const float*)d_in[2];
    const float* Wi     = (const float*)d_in[3];
    const float* bi     = (const float*)d_in[4];
    const float* ln1_g  = (const float*)d_in[5];
    const float* ln1_b  = (const float*)d_in[6];
    const float* Wqkv   = (const float*)d_in[7];
    const float* bqkv   = (const float*)d_in[8];
    const float* Wo     = (const float*)d_in[9];
    const float* bo     = (const float*)d_in[10];
    const float* ln2_g  = (const float*)d_in[11];
    const float* ln2_b  = (const float*)d_in[12];
    const float* W1     = (const float*)d_in[13];
    const float* b1     = (const float*)d_in[14];
    const float* W2     = (const float*)d_in[15];
    const float* b2     = (const float*)d_in[16];
    const float* Wout   = (const float*)d_in[17];
    const float* bout   = (const float*)d_in[18];

    float *x, *q, *k, *v;
    __half *ah, *fh, *wh;
    cudaGetSymbolAddress((void**)&x,  g_x);
    cudaGetSymbolAddress((void**)&q,  g_q);
    cudaGetSymbolAddress((void**)&k,  g_k);
    cudaGetSymbolAddress((void**)&v,  g_v);
    cudaGetSymbolAddress((void**)&ah, g_ah);
    cudaGetSymbolAddress((void**)&fh, g_fh);
    cudaGetSymbolAddress((void**)&wh, g_wh);

    cudaFuncSetAttribute(gemm_1p<1>, cudaFuncAttributeMaxDynamicSharedMemorySize, DYN_SB);
    cudaFuncSetAttribute(gemm_1p<2>, cudaFuncAttributeMaxDynamicSharedMemorySize, DYN_SB);
    cudaFuncSetAttribute(gemm_1p<3>, cudaFuncAttributeMaxDynamicSharedMemorySize, DYN_SB);
    cudaFuncSetAttribute(gemm_1p<4>, cudaFuncAttributeMaxDynamicSharedMemorySize, DYN_SB);
    cudaFuncSetAttribute(flash_k, cudaFuncAttributeMaxDynamicSharedMemorySize, FLASH_SB);

    const int tot_xc = MM * CC;

    // fp16 weight conversions
    tohalf_k<<<eg4(CC * CC), 256>>>((const float4*)Wi, (__half2*)(wh + OFF_WI), CC * CC / 4);
    tohalf_k<<<eg4(LL*3*CC*CC), 256>>>((const float4*)Wqkv, (__half2*)(wh + OFF_WQKV), LL*3*CC*CC/4);
    tohalf_k<<<eg4(LL*CC*CC), 256>>>((const float4*)Wo, (__half2*)(wh + OFF_WO), LL*CC*CC/4);
    tohalf_k<<<eg4(LL*FF*CC), 256>>>((const float4*)W1, (__half2*)(wh + OFF_W1), LL*FF*CC/4);
    tohalf_k<<<eg4(LL*CC*FF), 256>>>((const float4*)W2, (__half2*)(wh + OFF_W2), LL*CC*FF/4);

    // x = inputs @ Wi.T + bi + pos
    tohalf_k<<<eg4(tot_xc), 256>>>((const float4*)inputs, (__half2*)ah, tot_xc / 4);
    gemm_1p<1><<<dim3(CC/256, MM/128), 512, DYN_SB>>>(
        ah, wh + OFF_WI, bi, x, nullptr, pos, nullptr, nullptr, nullptr, CC, CC);

    for (int l = 0; l < LL; l++) {
        const size_t oq = OFF_WQKV + (size_t)l * 3 * CC * CC;
        const size_t oo = OFF_WO   + (size_t)l * CC * CC;
        const size_t o1 = OFF_W1   + (size_t)l * FF * CC;
        const size_t o2 = OFF_W2   + (size_t)l * CC * FF;

        layernorm_h_k<<<MM, 256>>>(x, ln1_g + l * CC, ln1_b + l * CC, ah);
        gemm_1p<2><<<dim3(3*CC/256, MM/128), 512, DYN_SB>>>(
            ah, wh + oq, bqkv + (size_t)l * 3 * CC, nullptr, nullptr, nullptr,
            q, k, v, 3 * CC, CC);

        flash_k<<<dim3(NN/64, BHN), 256, FLASH_SB>>>(q, k, v, mask, ah);

        gemm_1p<3><<<dim3(CC/256, MM/128), 512, DYN_SB>>>(
            ah, wh + oo, bo + (size_t)l * CC, x, nullptr, nullptr,
            nullptr, nullptr, nullptr, CC, CC);

        layernorm_h_k<<<MM, 256>>>(x, ln2_g + l * CC, ln2_b + l * CC, ah);
        gemm_1p<4><<<dim3(FF/256, MM/128), 512, DYN_SB>>>(
            ah, wh + o1, b1 + (size_t)l * FF, nullptr, fh, nullptr,
            nullptr, nullptr, nullptr, FF, CC);
        gemm_1p<3><<<dim3(CC/256, MM/128), 512, DYN_SB>>>(
            fh, wh + o2, b2 + (size_t)l * CC, x, nullptr, nullptr,
            nullptr, nullptr, nullptr, CC, FF);
    }

    final_k<<<MM, 64>>>(x, Wout, bout, (float*)d_out);
}